// round 16
// baseline (speedup 1.0000x reference)
#include <cuda_runtime.h>
#include <cuda_bf16.h>
#include <cstdint>

// ---------------- problem constants ----------------
#define NLAYERS 4
#define INSZ    80
#define DMODEL  512
#define NHEAD   8
#define DH      64
#define DFF     2048
#define BATCH   16
#define SMAX    512
#define NTOK    (BATCH * SMAX)   // 8192

typedef __nv_bfloat16 bf16;

// ---------------- scratch (device globals; no allocs allowed) ----------------
__device__ float g_h  [NTOK * DMODEL];       // hidden state (exact fp32, straight)
__device__ float g_ht [NTOK * DMODEL];       // tf32-rounded copy of h (K-permuted)
__device__ float g_qkv[NTOK * 3 * DMODEL];   // qkv (tf32-rounded, straight)
__device__ float g_ctx[NTOK * DMODEL];       // attention ctx (tf32-rounded, K-permuted)
__device__ float g_ff [NTOK * DFF];          // ff intermediate (tf32-rounded, K-permuted)
__device__ float g_pool[BATCH * 8 * DMODEL]; // pooling partials

// tf32-rounded weight copies (K-permuted)
__device__ float g_wq_r[NLAYERS * 3 * DMODEL * DMODEL];
__device__ float g_wo_r[NLAYERS * DMODEL * DMODEL];
__device__ float g_w1_r[NLAYERS * DFF * DMODEL];
__device__ float g_w2_r[NLAYERS * DMODEL * DFF];

enum { EPI_NONE = 0, EPI_PE = 1, EPI_RELU = 2, EPI_RES = 3, EPI_QKV = 4 };

// K-permutation within groups of 8: stored pos of original column w.
// Puts (w, w+4) at adjacent positions (2w, 2w+1) -> LDS.64 fragment loads.
__host__ __device__ __forceinline__ int perm8(int w) {
    return 2 * (w & 3) + ((w >> 2) & 1);
}
__device__ __forceinline__ int permc(int c) {
    return (c & ~7) | perm8(c & 7);
}

// ---------------- helpers -----------------------------------------------------
// tf32 m16n8k8 MMA (fp32 accum); operands pre-rounded fp32 bit-patterns
__device__ __forceinline__ void mma1688(float* d, const uint32_t* a, const uint32_t* b) {
    asm volatile(
        "mma.sync.aligned.m16n8k8.row.col.f32.tf32.tf32.f32 "
        "{%0,%1,%2,%3},{%4,%5,%6,%7},{%8,%9},{%0,%1,%2,%3};\n"
        : "+f"(d[0]), "+f"(d[1]), "+f"(d[2]), "+f"(d[3])
        : "r"(a[0]), "r"(a[1]), "r"(a[2]), "r"(a[3]), "r"(b[0]), "r"(b[1]));
}

__device__ __forceinline__ float roundtf(float f) {
    uint32_t u;
    asm("cvt.rna.tf32.f32 %0, %1;" : "=r"(u) : "f"(f));
    return __uint_as_float(u);
}

__device__ __forceinline__ float4 roundtf4(float4 v) {
    v.x = roundtf(v.x); v.y = roundtf(v.y);
    v.z = roundtf(v.z); v.w = roundtf(v.w);
    return v;
}

__device__ __forceinline__ void cp16(uint32_t saddr, const void* g) {
    asm volatile("cp.async.cg.shared.global [%0], [%1], 16;\n" :: "r"(saddr), "l"(g));
}
__device__ __forceinline__ void cp_commit() { asm volatile("cp.async.commit_group;\n"); }
template <int N>
__device__ __forceinline__ void cp_wait() {
    asm volatile("cp.async.wait_group %0;\n" :: "n"(N));
}

// ---------------- fp32 -> tf32-rounded + K-permuted copy kernel --------------
__global__ __launch_bounds__(256) void round_kernel(
    const float* __restrict__ src, float* __restrict__ dst)
{
    const int i = (blockIdx.x * 256 + threadIdx.x) * 4;
    float4 v = roundtf4(*(const float4*)(src + i));
    dst[permc(i + 0)] = v.x;
    dst[permc(i + 1)] = v.y;
    dst[permc(i + 2)] = v.z;
    dst[permc(i + 3)] = v.w;
}

// =============================================================================
// TF32 single-pass tensor-core GEMM, 3-stage cp.async, pre-rounded K-permuted
// operands. 128x128 CTA tile, 256 threads, warp tile 32x64.
// Fragment loads are LDS.64 thanks to the K-permutation.
// =============================================================================
#define BK    32
#define LDS36 36
#define APLNW (128 * LDS36)
#define BPLNW (128 * LDS36)
#define BUFW  (APLNW + BPLNW)
#define NSTG  3
#define GSMEM (NSTG * BUFW * 4)        // 110592 B

template <int EPI>
__global__ __launch_bounds__(256, 2) void bgemm_kernel(
    const float* __restrict__ A, const float* __restrict__ B,
    const float* __restrict__ bias, const float* __restrict__ res,
    float* __restrict__ C, int M, int N, int K)
{
    extern __shared__ uint32_t smu[];
    const uint32_t smbase = (uint32_t)__cvta_generic_to_shared(smu);

    const int tid = threadIdx.x;
    const int bm = blockIdx.y * 128;
    const int bn = blockIdx.x * 128;

    const int wid  = tid >> 5;
    const int wm   = wid & 3;
    const int wn   = wid >> 2;
    const int lane = tid & 31;
    const int g    = lane >> 2;
    const int tg   = lane & 3;

    const int lrow = tid >> 3;
    const int lc4  = (tid & 7) * 4;

    float acc[2][8][4];
#pragma unroll
    for (int i = 0; i < 2; i++)
#pragma unroll
        for (int j = 0; j < 8; j++)
#pragma unroll
            for (int r = 0; r < 4; r++) acc[i][j][r] = 0.0f;

    const int ntile = K / BK;

#define LOAD_TILE(T, STG)                                                         \
    {                                                                             \
        const int k0 = (T) * BK;                                                  \
        const uint32_t sb = smbase + (STG) * (BUFW * 4);                          \
        _Pragma("unroll")                                                         \
        for (int p = 0; p < 4; p++) {                                             \
            const int row = lrow + p * 32;                                        \
            cp16(sb + (row * LDS36 + lc4) * 4,                                    \
                 A + (size_t)(bm + row) * K + k0 + lc4);                          \
            cp16(sb + (APLNW + row * LDS36 + lc4) * 4,                            \
                 B + (size_t)(bn + row) * K + k0 + lc4);                          \
        }                                                                         \
    }

    LOAD_TILE(0, 0); cp_commit();
    LOAD_TILE(1, 1); cp_commit();

    int stg = 0;
    for (int t = 0; t < ntile; t++) {
        if (t + 1 < ntile) cp_wait<1>(); else cp_wait<0>();
        __syncthreads();

        if (t + 2 < ntile) {
            const int s2 = (stg + 2) % NSTG;
            LOAD_TILE(t + 2, s2);
            cp_commit();
        }

        const uint32_t* pA = smu + stg * BUFW;
        const uint32_t* pB = pA + APLNW;

#pragma unroll
        for (int kk = 0; kk < 4; kk++) {
            const int kc = kk * 8 + 2 * tg;     // stored (permuted) position
            uint32_t a[2][4], b[8][2];
#pragma unroll
            for (int mi = 0; mi < 2; mi++) {
                const int r = wm * 32 + mi * 16 + g;
                const uint2 x = *(const uint2*)&pA[r * LDS36 + kc];        // (k=tg, k=tg+4)
                const uint2 y = *(const uint2*)&pA[(r + 8) * LDS36 + kc];
                a[mi][0] = x.x; a[mi][2] = x.y;
                a[mi][1] = y.x; a[mi][3] = y.y;
            }
#pragma unroll
            for (int ni = 0; ni < 8; ni++) {
                const int r = wn * 64 + ni * 8 + g;
                const uint2 z = *(const uint2*)&pB[r * LDS36 + kc];
                b[ni][0] = z.x; b[ni][1] = z.y;
            }
#pragma unroll
            for (int mi = 0; mi < 2; mi++)
#pragma unroll
                for (int ni = 0; ni < 8; ni++)
                    mma1688(acc[mi][ni], a[mi], b[ni]);
        }
        stg = (stg + 1) % NSTG;
    }
#undef LOAD_TILE

    // ---- epilogue ----
#pragma unroll
    for (int mi = 0; mi < 2; mi++) {
#pragma unroll
        for (int ni = 0; ni < 8; ni++) {
            const int m = bm + wm * 32 + mi * 16 + g;
            const int n = bn + wn * 64 + ni * 8 + tg * 2;
            const float b0 = bias[n], b1 = bias[n + 1];
#pragma unroll
            for (int h = 0; h < 2; h++) {
                const int mm = m + h * 8;
                float v0 = acc[mi][ni][h * 2 + 0] + b0;
                float v1 = acc[mi][ni][h * 2 + 1] + b1;
                if (EPI == EPI_RELU) {
                    // ff is consumed as GEMM K -> store K-permuted
                    v0 = roundtf(fmaxf(v0, 0.0f));
                    v1 = roundtf(fmaxf(v1, 0.0f));
                    C[(size_t)mm * N + permc(n)]     = v0;
                    C[(size_t)mm * N + permc(n + 1)] = v1;
                } else {
                    if (EPI == EPI_QKV) { v0 = roundtf(v0); v1 = roundtf(v1); }
                    if (EPI == EPI_RES) {
                        const float* rp = res + (size_t)mm * N + n;
                        v0 += rp[0]; v1 += rp[1];
                    }
                    float* cp = C + (size_t)mm * N + n;
                    cp[0] = v0; cp[1] = v1;
                }
            }
        }
    }
}

// ---------------- fp32 SGEMM (embed, K=80): h straight + ht permuted ---------
__global__ __launch_bounds__(256) void embed_kernel(
    const float* __restrict__ A, const float* __restrict__ B,
    const float* __restrict__ bias,
    float* __restrict__ C, float* __restrict__ Ct, int M, int N, int K)
{
    __shared__ float As[16][132];
    __shared__ float Bs[16][132];

    const int tid = threadIdx.x;
    const int bm = blockIdx.y * 128;
    const int bn = blockIdx.x * 128;

    const int lr = tid >> 2;
    const int lc = (tid & 3) * 4;
    const int ty = tid >> 4;
    const int tx = tid & 15;

    float acc[8][8];
#pragma unroll
    for (int i = 0; i < 8; i++)
#pragma unroll
        for (int j = 0; j < 8; j++) acc[i][j] = 0.0f;

    for (int k0 = 0; k0 < K; k0 += 16) {
#pragma unroll
        for (int p = 0; p < 2; p++) {
            const int row = lr + p * 64;
            float4 a = *(const float4*)(A + (size_t)(bm + row) * K + k0 + lc);
            float4 b = *(const float4*)(B + (size_t)(bn + row) * K + k0 + lc);
            As[lc + 0][row] = a.x; As[lc + 1][row] = a.y;
            As[lc + 2][row] = a.z; As[lc + 3][row] = a.w;
            Bs[lc + 0][row] = b.x; Bs[lc + 1][row] = b.y;
            Bs[lc + 2][row] = b.z; Bs[lc + 3][row] = b.w;
        }
        __syncthreads();
#pragma unroll
        for (int kk = 0; kk < 16; kk++) {
            float a[8], b[8];
            *(float4*)(a)     = *(const float4*)&As[kk][ty * 8];
            *(float4*)(a + 4) = *(const float4*)&As[kk][ty * 8 + 4];
            *(float4*)(b)     = *(const float4*)&Bs[kk][tx * 8];
            *(float4*)(b + 4) = *(const float4*)&Bs[kk][tx * 8 + 4];
#pragma unroll
            for (int i = 0; i < 8; i++)
#pragma unroll
                for (int j = 0; j < 8; j++)
                    acc[i][j] += a[i] * b[j];
        }
        __syncthreads();
    }

    const int m0 = bm + ty * 8;
    const int n0 = bn + tx * 8;
    float bv[8];
#pragma unroll
    for (int j = 0; j < 8; j++) bv[j] = bias[n0 + j];

#pragma unroll
    for (int i = 0; i < 8; i++) {
        const int m = m0 + i;
        const int s = m & (SMAX - 1);
#pragma unroll
        for (int j = 0; j < 8; j++) {
            const int n = n0 + j;
            float v = acc[i][j] + bv[j];
            const int de = n & ~1;
            float ang = (float)s * expf((float)de * (-9.210340371976184f / 512.0f));
            v += (n & 1) ? cosf(ang) : sinf(ang);
            C[(size_t)m * N + n] = v;
            Ct[(size_t)m * N + permc(n)] = roundtf(v);
        }
    }
}

// =============================================================================
// Flash-style TF32 attention (R15). qkv straight; ctx written K-permuted.
// =============================================================================
#define ATQ   128
#define ALD   68
#define AQPL  (128 * ALD)
#define AKPL  (64 * ALD)
#define ATTN_SMEM ((2 * AQPL + 2 * AKPL) * 4)   // 104448 B

__global__ __launch_bounds__(256) void fattn_kernel(
    const float* __restrict__ qkv, const int* __restrict__ lens,
    float* __restrict__ ctx)
{
    extern __shared__ float sf[];
    float* sQ = sf;
    float* sK = sf + AQPL;
    float* sV = sf + AQPL + AKPL;      // transposed: [dh][key]
    float* sP = sf + AQPL + 2 * AKPL;
    const uint32_t* pQ = (const uint32_t*)sQ;
    const uint32_t* pK = (const uint32_t*)sK;
    const uint32_t* pV = (const uint32_t*)sV;
    const uint32_t* pP = (const uint32_t*)sP;

    const int qt = blockIdx.x;
    const int hd = blockIdx.y;
    const int b  = blockIdx.z;
    const int tid  = threadIdx.x;
    const int w    = tid >> 5;
    const int lane = tid & 31;
    const int g    = lane >> 2;
    const int tg   = lane & 3;
    const int len  = lens[b];

    const float* base = qkv + (size_t)b * SMAX * (3 * DMODEL);

#pragma unroll
    for (int p = 0; p < 8; p++) {
        const int cid = p * 256 + tid;
        const int r  = cid >> 4;
        const int c4 = (cid & 15) * 4;
        *(float4*)(sQ + r * ALD + c4) =
            *(const float4*)(base + (size_t)(qt * ATQ + r) * (3 * DMODEL) + hd * DH + c4);
    }

    float sfr[8][4];
    float ofr[8][4];
#pragma unroll
    for (int j = 0; j < 8; j++)
#pragma unroll
        for (int c = 0; c < 4; c++) ofr[j][c] = 0.0f;
    float m0 = -1e30f, m1 = -1e30f, l0 = 0.0f, l1 = 0.0f;

    const int qrow = w * 16;

    for (int kt = 0; kt < 8; kt++) {
        __syncthreads();
#pragma unroll
        for (int p = 0; p < 4; p++) {
            const int cid = p * 256 + tid;
            const int r  = cid >> 4;
            const int c4 = (cid & 15) * 4;
            const float* rowp = base + (size_t)(kt * 64 + r) * (3 * DMODEL) + hd * DH;
            *(float4*)(sK + r * ALD + c4) = *(const float4*)(rowp + DMODEL + c4);
            float4 vv = *(const float4*)(rowp + 2 * DMODEL + c4);
            sV[(c4 + 0) * ALD + r] = vv.x;
            sV[(c4 + 1) * ALD + r] = vv.y;
            sV[(c4 + 2) * ALD + r] = vv.z;
            sV[(c4 + 3) * ALD + r] = vv.w;
        }
        __syncthreads();

#pragma unroll
        for (int j = 0; j < 8; j++)
#pragma unroll
            for (int c = 0; c < 4; c++) sfr[j][c] = 0.0f;

#pragma unroll
        for (int kc = 0; kc < 8; kc++) {
            const int kcol = kc * 8 + tg;
            uint32_t a[4];
            a[0] = pQ[(qrow + g) * ALD + kcol];
            a[1] = pQ[(qrow + 8 + g) * ALD + kcol];
            a[2] = pQ[(qrow + g) * ALD + kcol + 4];
            a[3] = pQ[(qrow + 8 + g) * ALD + kcol + 4];
#pragma unroll
            for (int j = 0; j < 8; j++) {
                uint32_t bfr[2];
                bfr[0] = pK[(j * 8 + g) * ALD + kcol];
                bfr[1] = pK[(j * 8 + g) * ALD + kcol + 4];
                mma1688(sfr[j], a, bfr);
            }
        }

        float tmax0 = -1e30f, tmax1 = -1e30f;
#pragma unroll
        for (int j = 0; j < 8; j++) {
            const int col = kt * 64 + j * 8 + 2 * tg;
            const bool v0 = col < len, v1 = (col + 1) < len;
            sfr[j][0] = v0 ? sfr[j][0] * 0.125f : -1e9f;
            sfr[j][1] = v1 ? sfr[j][1] * 0.125f : -1e9f;
            sfr[j][2] = v0 ? sfr[j][2] * 0.125f : -1e9f;
            sfr[j][3] = v1 ? sfr[j][3] * 0.125f : -1e9f;
            tmax0 = fmaxf(tmax0, fmaxf(sfr[j][0], sfr[j][1]));
            tmax1 = fmaxf(tmax1, fmaxf(sfr[j][2], sfr[j][3]));
        }
        tmax0 = fmaxf(tmax0, __shfl_xor_sync(0xffffffffu, tmax0, 1));
        tmax0 = fmaxf(tmax0, __shfl_xor_sync(0xffffffffu, tmax0, 2));
        tmax1 = fmaxf(tmax1, __shfl_xor_sync(0xffffffffu, tmax1, 1));
        tmax1 = fmaxf(tmax1, __shfl_xor_sync(0xffffffffu, tmax1, 2));

        const float nm0 = fmaxf(m0, tmax0), nm1 = fmaxf(m1, tmax1);
        const float al0 = expf(m0 - nm0), al1 = expf(m1 - nm1);
        m0 = nm0; m1 = nm1;

        float rs0 = 0.0f, rs1 = 0.0f;
#pragma unroll
        for (int j = 0; j < 8; j++) {
            sfr[j][0] = expf(sfr[j][0] - nm0);
            sfr[j][1] = expf(sfr[j][1] - nm0);
            sfr[j][2] = expf(sfr[j][2] - nm1);
            sfr[j][3] = expf(sfr[j][3] - nm1);
            rs0 += sfr[j][0] + sfr[j][1];
            rs1 += sfr[j][2] + sfr[j][3];
        }
        rs0 += __shfl_xor_sync(0xffffffffu, rs0, 1);
        rs0 += __shfl_xor_sync(0xffffffffu, rs0, 2);
        rs1 += __shfl_xor_sync(0xffffffffu, rs1, 1);
        rs1 += __shfl_xor_sync(0xffffffffu, rs1, 2);
        l0 = l0 * al0 + rs0;
        l1 = l1 * al1 + rs1;

#pragma unroll
        for (int j = 0; j < 8; j++) {
            ofr[j][0] *= al0; ofr[j][1] *= al0;
            ofr[j][2] *= al1; ofr[j][3] *= al1;
        }

#pragma unroll
        for (int j = 0; j < 8; j++) {
            const int c0 = j * 8 + 2 * tg;
            sP[(qrow + g) * ALD + c0]         = roundtf(sfr[j][0]);
            sP[(qrow + g) * ALD + c0 + 1]     = roundtf(sfr[j][1]);
            sP[(qrow + 8 + g) * ALD + c0]     = roundtf(sfr[j][2]);
            sP[(qrow + 8 + g) * ALD + c0 + 1] = roundtf(sfr[j][3]);
        }
        __syncwarp();

#pragma unroll
        for (int kc = 0; kc < 8; kc++) {
            const int kcol = kc * 8 + tg;
            uint32_t aP[4];
            aP[0] = pP[(qrow + g) * ALD + kcol];
            aP[1] = pP[(qrow + 8 + g) * ALD + kcol];
            aP[2] = pP[(qrow + g) * ALD + kcol + 4];
            aP[3] = pP[(qrow + 8 + g) * ALD + kcol + 4];
#pragma unroll
            for (int j = 0; j < 8; j++) {
                uint32_t bV[2];
                bV[0] = pV[(j * 8 + g) * ALD + kcol];
                bV[1] = pV[(j * 8 + g) * ALD + kcol + 4];
                mma1688(ofr[j], aP, bV);
            }
        }
    }

    // ---- finalize: O /= l, write ctx tf32-rounded + K-permuted ----
    const float inv0 = 1.0f / l0, inv1 = 1.0f / l1;
    const int q0 = qt * ATQ + qrow + g;
#pragma unroll
    for (int j = 0; j < 8; j++) {
        const int cb = hd * DH + j * 8;
        const int p0c = cb + perm8(2 * tg);
        const int p1c = cb + perm8(2 * tg + 1);
        float* r0 = ctx + ((size_t)b * SMAX + q0) * DMODEL;
        r0[p0c] = roundtf(ofr[j][0] * inv0);
        r0[p1c] = roundtf(ofr[j][1] * inv0);
        float* r1 = ctx + ((size_t)b * SMAX + q0 + 8) * DMODEL;
        r1[p0c] = roundtf(ofr[j][2] * inv1);
        r1[p1c] = roundtf(ofr[j][3] * inv1);
    }
}

// ---------------- LayerNorm (in place) + rounded K-permuted copy --------------
__global__ __launch_bounds__(128) void ln_kernel(
    float* __restrict__ h, const float* __restrict__ g, const float* __restrict__ bta,
    float* __restrict__ ht)
{
    __shared__ float red[8];
    const int row = blockIdx.x;
    const int t = threadIdx.x;
    float* p = h + (size_t)row * DMODEL + t * 4;
    float4 v = *(float4*)p;
    float s  = v.x + v.y + v.z + v.w;
    float ss = v.x * v.x + v.y * v.y + v.z * v.z + v.w * v.w;
#pragma unroll
    for (int o = 16; o; o >>= 1) {
        s  += __shfl_xor_sync(0xffffffffu, s, o);
        ss += __shfl_xor_sync(0xffffffffu, ss, o);
    }
    const int w = t >> 5;
    if ((t & 31) == 0) { red[w] = s; red[4 + w] = ss; }
    __syncthreads();
    s  = red[0] + red[1] + red[2] + red[3];
    ss = red[4] + red[5] + red[6] + red[7];
    const float mean = s * (1.0f / DMODEL);
    const float var  = ss * (1.0f / DMODEL) - mean * mean;
    const float rstd = rsqrtf(var + 1e-5f);
    float4 gg = *(const float4*)(g + t * 4);
    float4 bb = *(const float4*)(bta + t * 4);
    v.x = (v.x - mean) * rstd * gg.x + bb.x;
    v.y = (v.y - mean) * rstd * gg.y + bb.y;
    v.z = (v.z - mean) * rstd * gg.z + bb.z;
    v.w = (v.w - mean) * rstd * gg.w + bb.w;
    *(float4*)p = v;
    float* hp = ht + (size_t)row * DMODEL;
    const int c = t * 4;
    hp[permc(c + 0)] = roundtf(v.x);
    hp[permc(c + 1)] = roundtf(v.y);
    hp[permc(c + 2)] = roundtf(v.z);
    hp[permc(c + 3)] = roundtf(v.w);
}

// ---------------- two-phase masked mean pooling ------------------------------
__global__ __launch_bounds__(128) void pool_part_kernel(
    const float* __restrict__ h, const int* __restrict__ lens, float* __restrict__ part)
{
    const int b = blockIdx.x;
    const int ch = blockIdx.y;
    const int d = threadIdx.x * 4;
    const int len = lens[b];
    const int t0 = ch * 64;
    int nt = len - t0;
    if (nt > 64) nt = 64;
    float4 s = {0.f, 0.f, 0.f, 0.f};
    for (int t = 0; t < nt; t++) {
        float4 v = *(const float4*)(h + ((size_t)b * SMAX + t0 + t) * DMODEL + d);
        s.x += v.x; s.y += v.y; s.z += v.z; s.w += v.w;
    }
    *(float4*)(part + (size_t)(b * 8 + ch) * DMODEL + d) = s;
}

__global__ __launch_bounds__(DMODEL) void pool_final_kernel(
    const float* __restrict__ part, const int* __restrict__ lens,
    float* __restrict__ out, int out_size)
{
    const int b = blockIdx.x;
    const int d = threadIdx.x;
    float s = 0.0f;
#pragma unroll
    for (int c = 0; c < 8; c++) s += part[(size_t)(b * 8 + c) * DMODEL + d];
    out[b * DMODEL + d] = s / (float)lens[b];
    if (d == 0 && out_size >= BATCH * DMODEL + BATCH)
        out[BATCH * DMODEL + b] = (float)lens[b];
}

// ---------------- launch ------------------------------------------------------
extern "C" void kernel_launch(void* const* d_in, const int* in_sizes, int n_in,
                              void* d_out, int out_size)
{
    (void)in_sizes; (void)n_in;
    const float* x     = (const float*)d_in[0];
    const int*   lens  = (const int*)  d_in[1];
    const float* We    = (const float*)d_in[2];
    const float* be    = (const float*)d_in[3];
    const float* Wqkv  = (const float*)d_in[4];
    const float* bqkv  = (const float*)d_in[5];
    const float* Wo    = (const float*)d_in[6];
    const float* bo    = (const float*)d_in[7];
    const float* ln1g  = (const float*)d_in[8];
    const float* ln1b  = (const float*)d_in[9];
    const float* W1    = (const float*)d_in[10];
    const float* b1    = (const float*)d_in[11];
    const float* W2    = (const float*)d_in[12];
    const float* b2    = (const float*)d_in[13];
    const float* ln2g  = (const float*)d_in[14];
    const float* ln2b  = (const float*)d_in[15];
    float* out = (float*)d_out;

    void *ph, *pht, *pqkv, *pctx, *pff, *ppool;
    void *pwq, *pwo, *pw1, *pw2;
    cudaGetSymbolAddress(&ph,    g_h);
    cudaGetSymbolAddress(&pht,   g_ht);
    cudaGetSymbolAddress(&pqkv,  g_qkv);
    cudaGetSymbolAddress(&pctx,  g_ctx);
    cudaGetSymbolAddress(&pff,   g_ff);
    cudaGetSymbolAddress(&ppool, g_pool);
    cudaGetSymbolAddress(&pwq,   g_wq_r);
    cudaGetSymbolAddress(&pwo,   g_wo_r);
    cudaGetSymbolAddress(&pw1,   g_w1_r);
    cudaGetSymbolAddress(&pw2,   g_w2_r);
    float* h    = (float*)ph;
    float* ht   = (float*)pht;
    float* qkv  = (float*)pqkv;
    float* ctx  = (float*)pctx;
    float* ff   = (float*)pff;
    float* pool = (float*)ppool;
    float* wq_r = (float*)pwq;
    float* wo_r = (float*)pwo;
    float* w1_r = (float*)pw1;
    float* w2_r = (float*)pw2;

    cudaFuncSetAttribute(fattn_kernel,
                         cudaFuncAttributeMaxDynamicSharedMemorySize, ATTN_SMEM);
    cudaFuncSetAttribute(bgemm_kernel<EPI_QKV>,
                         cudaFuncAttributeMaxDynamicSharedMemorySize, GSMEM);
    cudaFuncSetAttribute(bgemm_kernel<EPI_RELU>,
                         cudaFuncAttributeMaxDynamicSharedMemorySize, GSMEM);
    cudaFuncSetAttribute(bgemm_kernel<EPI_RES>,
                         cudaFuncAttributeMaxDynamicSharedMemorySize, GSMEM);

    // ---- round + K-permute weights (once per launch) ----
    round_kernel<<<NLAYERS * 3 * DMODEL * DMODEL / 1024, 256>>>(Wqkv, wq_r);
    round_kernel<<<NLAYERS * DMODEL * DMODEL / 1024, 256>>>(Wo, wo_r);
    round_kernel<<<NLAYERS * DFF * DMODEL / 1024, 256>>>(W1, w1_r);
    round_kernel<<<NLAYERS * DMODEL * DFF / 1024, 256>>>(W2, w2_r);

    // embedding + positional encoding: h (straight) + ht (permuted)
    embed_kernel<<<dim3(DMODEL / 128, NTOK / 128), 256>>>(
        x, We, be, h, ht, NTOK, DMODEL, INSZ);

    for (int l = 0; l < NLAYERS; l++) {
        const float* wq  = wq_r + (size_t)l * 3 * DMODEL * DMODEL;
        const float* bq  = bqkv + (size_t)l * 3 * DMODEL;
        const float* wo  = wo_r + (size_t)l * DMODEL * DMODEL;
        const float* bO  = bo   + (size_t)l * DMODEL;
        const float* w1  = w1_r + (size_t)l * DFF * DMODEL;
        const float* bf1 = b1   + (size_t)l * DFF;
        const float* w2  = w2_r + (size_t)l * DMODEL * DFF;
        const float* bf2 = b2   + (size_t)l * DMODEL;

        // qkv = round(ht @ wq^T + bq)  (straight, feeds attention)
        bgemm_kernel<EPI_QKV><<<dim3(3 * DMODEL / 128, NTOK / 128), 256, GSMEM>>>(
            ht, wq, bq, nullptr, qkv, NTOK, 3 * DMODEL, DMODEL);

        // attention -> ctx (tf32-rounded, K-permuted)
        fattn_kernel<<<dim3(SMAX / ATQ, NHEAD, BATCH), 256, ATTN_SMEM>>>(qkv, lens, ctx);

        // h = h + ctx @ wo^T + bo
        bgemm_kernel<EPI_RES><<<dim3(DMODEL / 128, NTOK / 128), 256, GSMEM>>>(
            ctx, wo, bO, h, h, NTOK, DMODEL, DMODEL);
        ln_kernel<<<NTOK, 128>>>(h, ln1g + l * DMODEL, ln1b + l * DMODEL, ht);

        // ff = round(relu(ht @ w1^T + b1))  (K-permuted)
        bgemm_kernel<EPI_RELU><<<dim3(DFF / 128, NTOK / 128), 256, GSMEM>>>(
            ht, w1, bf1, nullptr, ff, NTOK, DFF, DMODEL);
        // h = h + ff @ w2^T + b2
        bgemm_kernel<EPI_RES><<<dim3(DMODEL / 128, NTOK / 128), 256, GSMEM>>>(
            ff, w2, bf2, h, h, NTOK, DMODEL, DFF);
        ln_kernel<<<NTOK, 128>>>(h, ln2g + l * DMODEL, ln2b + l * DMODEL, ht);
    }

    pool_part_kernel<<<dim3(BATCH, 8), 128>>>(h, lens, pool);
    pool_final_kernel<<<BATCH, DMODEL>>>(pool, lens, out, out_size);
}

// round 17
// speedup vs baseline: 1.2084x; 1.2084x over previous
#include <cuda_runtime.h>
#include <cuda_bf16.h>
#include <cstdint>

// ---------------- problem constants ----------------
#define NLAYERS 4
#define INSZ    80
#define DMODEL  512
#define NHEAD   8
#define DH      64
#define DFF     2048
#define BATCH   16
#define SMAX    512
#define NTOK    (BATCH * SMAX)   // 8192

typedef __nv_bfloat16 bf16;

// ---------------- scratch (device globals; no allocs allowed) ----------------
__device__ float g_h  [NTOK * DMODEL];       // hidden state (exact fp32)
__device__ float g_ht [NTOK * DMODEL];       // tf32-rounded copy of h
__device__ float g_qkv[NTOK * 3 * DMODEL];   // qkv projections (tf32-rounded)
__device__ float g_ctx[NTOK * DMODEL];       // attention context (tf32-rounded)
__device__ float g_ff [NTOK * DFF];          // ff intermediate (tf32-rounded)
__device__ float g_pool[BATCH * 8 * DMODEL]; // pooling partials

// tf32-rounded weight copies
__device__ float g_wq_r[NLAYERS * 3 * DMODEL * DMODEL];
__device__ float g_wo_r[NLAYERS * DMODEL * DMODEL];
__device__ float g_w1_r[NLAYERS * DFF * DMODEL];
__device__ float g_w2_r[NLAYERS * DMODEL * DFF];

enum { EPI_NONE = 0, EPI_PE = 1, EPI_RELU = 2, EPI_RES = 3, EPI_QKV = 4 };

// ---------------- helpers -----------------------------------------------------
// tf32 m16n8k8 MMA (fp32 accum); operands pre-rounded fp32 bit-patterns
__device__ __forceinline__ void mma1688(float* d, const uint32_t* a, const uint32_t* b) {
    asm volatile(
        "mma.sync.aligned.m16n8k8.row.col.f32.tf32.tf32.f32 "
        "{%0,%1,%2,%3},{%4,%5,%6,%7},{%8,%9},{%0,%1,%2,%3};\n"
        : "+f"(d[0]), "+f"(d[1]), "+f"(d[2]), "+f"(d[3])
        : "r"(a[0]), "r"(a[1]), "r"(a[2]), "r"(a[3]), "r"(b[0]), "r"(b[1]));
}

__device__ __forceinline__ float roundtf(float f) {
    uint32_t u;
    asm("cvt.rna.tf32.f32 %0, %1;" : "=r"(u) : "f"(f));
    return __uint_as_float(u);
}

__device__ __forceinline__ float4 roundtf4(float4 v) {
    v.x = roundtf(v.x); v.y = roundtf(v.y);
    v.z = roundtf(v.z); v.w = roundtf(v.w);
    return v;
}

__device__ __forceinline__ void cp16(uint32_t saddr, const void* g) {
    asm volatile("cp.async.cg.shared.global [%0], [%1], 16;\n" :: "r"(saddr), "l"(g));
}
__device__ __forceinline__ void cp_commit() { asm volatile("cp.async.commit_group;\n"); }
template <int N>
__device__ __forceinline__ void cp_wait() {
    asm volatile("cp.async.wait_group %0;\n" :: "n"(N));
}

// ---------------- fp32 -> tf32-rounded copy kernel ---------------------------
__global__ __launch_bounds__(256) void round_kernel(
    const float* __restrict__ src, float* __restrict__ dst)
{
    const int i = (blockIdx.x * 256 + threadIdx.x) * 4;
    *(float4*)(dst + i) = roundtf4(*(const float4*)(src + i));
}

// =============================================================================
// TF32 single-pass tensor-core GEMM, 3-stage cp.async, pre-rounded operands.
// 128x128 CTA tile, 256 threads, warp tile 32x64 (4m x 2n). (R13, proven)
// =============================================================================
#define BK    32
#define LDS36 36
#define APLNW (128 * LDS36)
#define BPLNW (128 * LDS36)
#define BUFW  (APLNW + BPLNW)
#define NSTG  3
#define GSMEM (NSTG * BUFW * 4)        // 110592 B

template <int EPI>
__global__ __launch_bounds__(256, 2) void bgemm_kernel(
    const float* __restrict__ A, const float* __restrict__ B,
    const float* __restrict__ bias, const float* __restrict__ res,
    float* __restrict__ C, int M, int N, int K)
{
    extern __shared__ uint32_t smu[];
    const uint32_t smbase = (uint32_t)__cvta_generic_to_shared(smu);

    const int tid = threadIdx.x;
    const int bm = blockIdx.y * 128;
    const int bn = blockIdx.x * 128;

    const int wid  = tid >> 5;
    const int wm   = wid & 3;
    const int wn   = wid >> 2;
    const int lane = tid & 31;
    const int g    = lane >> 2;
    const int tg   = lane & 3;

    const int lrow = tid >> 3;
    const int lc4  = (tid & 7) * 4;

    float acc[2][8][4];
#pragma unroll
    for (int i = 0; i < 2; i++)
#pragma unroll
        for (int j = 0; j < 8; j++)
#pragma unroll
            for (int r = 0; r < 4; r++) acc[i][j][r] = 0.0f;

    const int ntile = K / BK;

#define LOAD_TILE(T, STG)                                                         \
    {                                                                             \
        const int k0 = (T) * BK;                                                  \
        const uint32_t sb = smbase + (STG) * (BUFW * 4);                          \
        _Pragma("unroll")                                                         \
        for (int p = 0; p < 4; p++) {                                             \
            const int row = lrow + p * 32;                                        \
            cp16(sb + (row * LDS36 + lc4) * 4,                                    \
                 A + (size_t)(bm + row) * K + k0 + lc4);                          \
            cp16(sb + (APLNW + row * LDS36 + lc4) * 4,                            \
                 B + (size_t)(bn + row) * K + k0 + lc4);                          \
        }                                                                         \
    }

    LOAD_TILE(0, 0); cp_commit();
    LOAD_TILE(1, 1); cp_commit();

    int stg = 0;
    for (int t = 0; t < ntile; t++) {
        if (t + 1 < ntile) cp_wait<1>(); else cp_wait<0>();
        __syncthreads();

        if (t + 2 < ntile) {
            const int s2 = (stg + 2) % NSTG;
            LOAD_TILE(t + 2, s2);
            cp_commit();
        }

        const uint32_t* pA = smu + stg * BUFW;
        const uint32_t* pB = pA + APLNW;

#pragma unroll
        for (int kk = 0; kk < 4; kk++) {
            const int kc = kk * 8 + tg;
            uint32_t a[2][4], b[8][2];
#pragma unroll
            for (int mi = 0; mi < 2; mi++) {
                const int r = wm * 32 + mi * 16 + g;
                a[mi][0] = pA[r * LDS36 + kc];
                a[mi][1] = pA[(r + 8) * LDS36 + kc];
                a[mi][2] = pA[r * LDS36 + kc + 4];
                a[mi][3] = pA[(r + 8) * LDS36 + kc + 4];
            }
#pragma unroll
            for (int ni = 0; ni < 8; ni++) {
                const int r = wn * 64 + ni * 8 + g;
                b[ni][0] = pB[r * LDS36 + kc];
                b[ni][1] = pB[r * LDS36 + kc + 4];
            }
#pragma unroll
            for (int mi = 0; mi < 2; mi++)
#pragma unroll
                for (int ni = 0; ni < 8; ni++)
                    mma1688(acc[mi][ni], a[mi], b[ni]);
        }
        stg = (stg + 1) % NSTG;
    }
#undef LOAD_TILE

    // ---- epilogue ----
#pragma unroll
    for (int mi = 0; mi < 2; mi++) {
#pragma unroll
        for (int ni = 0; ni < 8; ni++) {
            const int m = bm + wm * 32 + mi * 16 + g;
            const int n = bn + wn * 64 + ni * 8 + tg * 2;
            const float b0 = bias[n], b1 = bias[n + 1];
#pragma unroll
            for (int h = 0; h < 2; h++) {
                const int mm = m + h * 8;
                float v0 = acc[mi][ni][h * 2 + 0] + b0;
                float v1 = acc[mi][ni][h * 2 + 1] + b1;
                if (EPI == EPI_RELU) {
                    v0 = roundtf(fmaxf(v0, 0.0f));
                    v1 = roundtf(fmaxf(v1, 0.0f));
                }
                if (EPI == EPI_QKV) {
                    v0 = roundtf(v0);
                    v1 = roundtf(v1);
                }
                if (EPI == EPI_RES) {
                    const float* rp = res + (size_t)mm * N + n;
                    v0 += rp[0]; v1 += rp[1];
                }
                float* cp = C + (size_t)mm * N + n;
                cp[0] = v0; cp[1] = v1;
            }
        }
    }
}

// ---------------- fp32 SGEMM (embed, K=80), writes h exact + h_t rounded -----
__global__ __launch_bounds__(256) void embed_kernel(
    const float* __restrict__ A, const float* __restrict__ B,
    const float* __restrict__ bias,
    float* __restrict__ C, float* __restrict__ Ct, int M, int N, int K)
{
    __shared__ float As[16][132];
    __shared__ float Bs[16][132];

    const int tid = threadIdx.x;
    const int bm = blockIdx.y * 128;
    const int bn = blockIdx.x * 128;

    const int lr = tid >> 2;
    const int lc = (tid & 3) * 4;
    const int ty = tid >> 4;
    const int tx = tid & 15;

    float acc[8][8];
#pragma unroll
    for (int i = 0; i < 8; i++)
#pragma unroll
        for (int j = 0; j < 8; j++) acc[i][j] = 0.0f;

    for (int k0 = 0; k0 < K; k0 += 16) {
#pragma unroll
        for (int p = 0; p < 2; p++) {
            const int row = lr + p * 64;
            float4 a = *(const float4*)(A + (size_t)(bm + row) * K + k0 + lc);
            float4 b = *(const float4*)(B + (size_t)(bn + row) * K + k0 + lc);
            As[lc + 0][row] = a.x; As[lc + 1][row] = a.y;
            As[lc + 2][row] = a.z; As[lc + 3][row] = a.w;
            Bs[lc + 0][row] = b.x; Bs[lc + 1][row] = b.y;
            Bs[lc + 2][row] = b.z; Bs[lc + 3][row] = b.w;
        }
        __syncthreads();
#pragma unroll
        for (int kk = 0; kk < 16; kk++) {
            float a[8], b[8];
            *(float4*)(a)     = *(const float4*)&As[kk][ty * 8];
            *(float4*)(a + 4) = *(const float4*)&As[kk][ty * 8 + 4];
            *(float4*)(b)     = *(const float4*)&Bs[kk][tx * 8];
            *(float4*)(b + 4) = *(const float4*)&Bs[kk][tx * 8 + 4];
#pragma unroll
            for (int i = 0; i < 8; i++)
#pragma unroll
                for (int j = 0; j < 8; j++)
                    acc[i][j] += a[i] * b[j];
        }
        __syncthreads();
    }

    const int m0 = bm + ty * 8;
    const int n0 = bn + tx * 8;
    float bv[8];
#pragma unroll
    for (int j = 0; j < 8; j++) bv[j] = bias[n0 + j];

#pragma unroll
    for (int i = 0; i < 8; i++) {
        const int m = m0 + i;
        const int s = m & (SMAX - 1);
#pragma unroll
        for (int j = 0; j < 8; j++) {
            const int n = n0 + j;
            float v = acc[i][j] + bv[j];
            const int de = n & ~1;
            float ang = (float)s * expf((float)de * (-9.210340371976184f / 512.0f));
            v += (n & 1) ? cosf(ang) : sinf(ang);
            const size_t ix = (size_t)m * N + n;
            C[ix]  = v;
            Ct[ix] = roundtf(v);
        }
    }
}

// =============================================================================
// Flash-style TF32 attention. CTA = (128 q, head, batch), 256 thr (8 warps).
// Fully-masked key tiles (kt*64 >= len) are skipped: they contribute exactly
// zero (all lanes -1e9 -> exp underflows to 0, max unchanged since len >= 256
// guarantees real tiles first). Bit-identical to processing them.
// =============================================================================
#define ATQ   128
#define ALD   68                       // fp32 words per row (64 + 4 pad)
#define AQPL  (128 * ALD)              // Q / P pane words
#define AKPL  (64 * ALD)               // K / V pane words
#define ATTN_SMEM ((2 * AQPL + 2 * AKPL) * 4)   // 104448 B

__global__ __launch_bounds__(256) void fattn_kernel(
    const float* __restrict__ qkv, const int* __restrict__ lens,
    float* __restrict__ ctx)
{
    extern __shared__ float sf[];
    float* sQ = sf;                    // [128][68]
    float* sK = sf + AQPL;             // [64][68]
    float* sV = sf + AQPL + AKPL;      // transposed: [dh][key]
    float* sP = sf + AQPL + 2 * AKPL;  // [128][68]
    const uint32_t* pQ = (const uint32_t*)sQ;
    const uint32_t* pK = (const uint32_t*)sK;
    const uint32_t* pV = (const uint32_t*)sV;
    const uint32_t* pP = (const uint32_t*)sP;

    const int qt = blockIdx.x;
    const int hd = blockIdx.y;
    const int b  = blockIdx.z;
    const int tid  = threadIdx.x;
    const int w    = tid >> 5;
    const int lane = tid & 31;
    const int g    = lane >> 2;
    const int tg   = lane & 3;
    const int len  = lens[b];
    const int ktmax = (len + 63) >> 6;   // uniform per CTA (len per batch)

    const float* base = qkv + (size_t)b * SMAX * (3 * DMODEL);

    // ---- load Q tile [128 x 64] (already tf32-rounded) ----
#pragma unroll
    for (int p = 0; p < 8; p++) {
        const int cid = p * 256 + tid;
        const int r  = cid >> 4;
        const int c4 = (cid & 15) * 4;
        *(float4*)(sQ + r * ALD + c4) =
            *(const float4*)(base + (size_t)(qt * ATQ + r) * (3 * DMODEL) + hd * DH + c4);
    }

    float sfr[8][4];
    float ofr[8][4];
#pragma unroll
    for (int j = 0; j < 8; j++)
#pragma unroll
        for (int c = 0; c < 4; c++) ofr[j][c] = 0.0f;
    float m0 = -1e30f, m1 = -1e30f, l0 = 0.0f, l1 = 0.0f;

    const int qrow = w * 16;

    for (int kt = 0; kt < ktmax; kt++) {
        __syncthreads();
        // ---- load K tile + V tile (transposed), plain copies ----
#pragma unroll
        for (int p = 0; p < 4; p++) {
            const int cid = p * 256 + tid;
            const int r  = cid >> 4;
            const int c4 = (cid & 15) * 4;
            const float* rowp = base + (size_t)(kt * 64 + r) * (3 * DMODEL) + hd * DH;
            *(float4*)(sK + r * ALD + c4) = *(const float4*)(rowp + DMODEL + c4);
            float4 vv = *(const float4*)(rowp + 2 * DMODEL + c4);
            sV[(c4 + 0) * ALD + r] = vv.x;
            sV[(c4 + 1) * ALD + r] = vv.y;
            sV[(c4 + 2) * ALD + r] = vv.z;
            sV[(c4 + 3) * ALD + r] = vv.w;
        }
        __syncthreads();

        // ---- S = Q K^T (single-pass tf32) ----
#pragma unroll
        for (int j = 0; j < 8; j++)
#pragma unroll
            for (int c = 0; c < 4; c++) sfr[j][c] = 0.0f;

#pragma unroll
        for (int kc = 0; kc < 8; kc++) {
            const int kcol = kc * 8 + tg;
            uint32_t a[4];
            a[0] = pQ[(qrow + g) * ALD + kcol];
            a[1] = pQ[(qrow + 8 + g) * ALD + kcol];
            a[2] = pQ[(qrow + g) * ALD + kcol + 4];
            a[3] = pQ[(qrow + 8 + g) * ALD + kcol + 4];
#pragma unroll
            for (int j = 0; j < 8; j++) {
                uint32_t bfr[2];
                bfr[0] = pK[(j * 8 + g) * ALD + kcol];
                bfr[1] = pK[(j * 8 + g) * ALD + kcol + 4];
                mma1688(sfr[j], a, bfr);
            }
        }

        // ---- scale + mask + online softmax update ----
        float tmax0 = -1e30f, tmax1 = -1e30f;
#pragma unroll
        for (int j = 0; j < 8; j++) {
            const int col = kt * 64 + j * 8 + 2 * tg;
            const bool v0 = col < len, v1 = (col + 1) < len;
            sfr[j][0] = v0 ? sfr[j][0] * 0.125f : -1e9f;
            sfr[j][1] = v1 ? sfr[j][1] * 0.125f : -1e9f;
            sfr[j][2] = v0 ? sfr[j][2] * 0.125f : -1e9f;
            sfr[j][3] = v1 ? sfr[j][3] * 0.125f : -1e9f;
            tmax0 = fmaxf(tmax0, fmaxf(sfr[j][0], sfr[j][1]));
            tmax1 = fmaxf(tmax1, fmaxf(sfr[j][2], sfr[j][3]));
        }
        tmax0 = fmaxf(tmax0, __shfl_xor_sync(0xffffffffu, tmax0, 1));
        tmax0 = fmaxf(tmax0, __shfl_xor_sync(0xffffffffu, tmax0, 2));
        tmax1 = fmaxf(tmax1, __shfl_xor_sync(0xffffffffu, tmax1, 1));
        tmax1 = fmaxf(tmax1, __shfl_xor_sync(0xffffffffu, tmax1, 2));

        const float nm0 = fmaxf(m0, tmax0), nm1 = fmaxf(m1, tmax1);
        const float al0 = expf(m0 - nm0), al1 = expf(m1 - nm1);
        m0 = nm0; m1 = nm1;

        float rs0 = 0.0f, rs1 = 0.0f;
#pragma unroll
        for (int j = 0; j < 8; j++) {
            sfr[j][0] = expf(sfr[j][0] - nm0);
            sfr[j][1] = expf(sfr[j][1] - nm0);
            sfr[j][2] = expf(sfr[j][2] - nm1);
            sfr[j][3] = expf(sfr[j][3] - nm1);
            rs0 += sfr[j][0] + sfr[j][1];
            rs1 += sfr[j][2] + sfr[j][3];
        }
        rs0 += __shfl_xor_sync(0xffffffffu, rs0, 1);
        rs0 += __shfl_xor_sync(0xffffffffu, rs0, 2);
        rs1 += __shfl_xor_sync(0xffffffffu, rs1, 1);
        rs1 += __shfl_xor_sync(0xffffffffu, rs1, 2);
        l0 = l0 * al0 + rs0;
        l1 = l1 * al1 + rs1;

#pragma unroll
        for (int j = 0; j < 8; j++) {
            ofr[j][0] *= al0; ofr[j][1] *= al0;
            ofr[j][2] *= al1; ofr[j][3] *= al1;
        }

        // ---- round P into warp-private smem pane ----
#pragma unroll
        for (int j = 0; j < 8; j++) {
            const int c0 = j * 8 + 2 * tg;
            sP[(qrow + g) * ALD + c0]         = roundtf(sfr[j][0]);
            sP[(qrow + g) * ALD + c0 + 1]     = roundtf(sfr[j][1]);
            sP[(qrow + 8 + g) * ALD + c0]     = roundtf(sfr[j][2]);
            sP[(qrow + 8 + g) * ALD + c0 + 1] = roundtf(sfr[j][3]);
        }
        __syncwarp();

        // ---- O += P V (single-pass tf32) ----
#pragma unroll
        for (int kc = 0; kc < 8; kc++) {
            const int kcol = kc * 8 + tg;
            uint32_t aP[4];
            aP[0] = pP[(qrow + g) * ALD + kcol];
            aP[1] = pP[(qrow + 8 + g) * ALD + kcol];
            aP[2] = pP[(qrow + g) * ALD + kcol + 4];
            aP[3] = pP[(qrow + 8 + g) * ALD + kcol + 4];
#pragma unroll
            for (int j = 0; j < 8; j++) {
                uint32_t bV[2];
                bV[0] = pV[(j * 8 + g) * ALD + kcol];
                bV[1] = pV[(j * 8 + g) * ALD + kcol + 4];
                mma1688(ofr[j], aP, bV);
            }
        }
    }

    // ---- finalize: O /= l, write ctx tf32-rounded ----
    const float inv0 = 1.0f / l0, inv1 = 1.0f / l1;
    const int q0 = qt * ATQ + qrow + g;
#pragma unroll
    for (int j = 0; j < 8; j++) {
        const int col = hd * DH + j * 8 + 2 * tg;
        float* p0 = ctx + ((size_t)b * SMAX + q0) * DMODEL + col;
        p0[0] = roundtf(ofr[j][0] * inv0);
        p0[1] = roundtf(ofr[j][1] * inv0);
        float* p1 = ctx + ((size_t)b * SMAX + q0 + 8) * DMODEL + col;
        p1[0] = roundtf(ofr[j][2] * inv1);
        p1[1] = roundtf(ofr[j][3] * inv1);
    }
}

// ---------------- LayerNorm (in place) + rounded copy -------------------------
__global__ __launch_bounds__(128) void ln_kernel(
    float* __restrict__ h, const float* __restrict__ g, const float* __restrict__ bta,
    float* __restrict__ ht)
{
    __shared__ float red[8];
    const int row = blockIdx.x;
    const int t = threadIdx.x;
    float* p = h + (size_t)row * DMODEL + t * 4;
    float4 v = *(float4*)p;
    float s  = v.x + v.y + v.z + v.w;
    float ss = v.x * v.x + v.y * v.y + v.z * v.z + v.w * v.w;
#pragma unroll
    for (int o = 16; o; o >>= 1) {
        s  += __shfl_xor_sync(0xffffffffu, s, o);
        ss += __shfl_xor_sync(0xffffffffu, ss, o);
    }
    const int w = t >> 5;
    if ((t & 31) == 0) { red[w] = s; red[4 + w] = ss; }
    __syncthreads();
    s  = red[0] + red[1] + red[2] + red[3];
    ss = red[4] + red[5] + red[6] + red[7];
    const float mean = s * (1.0f / DMODEL);
    const float var  = ss * (1.0f / DMODEL) - mean * mean;
    const float rstd = rsqrtf(var + 1e-5f);
    float4 gg = *(const float4*)(g + t * 4);
    float4 bb = *(const float4*)(bta + t * 4);
    v.x = (v.x - mean) * rstd * gg.x + bb.x;
    v.y = (v.y - mean) * rstd * gg.y + bb.y;
    v.z = (v.z - mean) * rstd * gg.z + bb.z;
    v.w = (v.w - mean) * rstd * gg.w + bb.w;
    *(float4*)p = v;
    *(float4*)(ht + (size_t)row * DMODEL + t * 4) = roundtf4(v);
}

// ---------------- two-phase masked mean pooling ------------------------------
__global__ __launch_bounds__(128) void pool_part_kernel(
    const float* __restrict__ h, const int* __restrict__ lens, float* __restrict__ part)
{
    const int b = blockIdx.x;
    const int ch = blockIdx.y;
    const int d = threadIdx.x * 4;
    const int len = lens[b];
    const int t0 = ch * 64;
    int nt = len - t0;
    if (nt > 64) nt = 64;
    float4 s = {0.f, 0.f, 0.f, 0.f};
    for (int t = 0; t < nt; t++) {
        float4 v = *(const float4*)(h + ((size_t)b * SMAX + t0 + t) * DMODEL + d);
        s.x += v.x; s.y += v.y; s.z += v.z; s.w += v.w;
    }
    *(float4*)(part + (size_t)(b * 8 + ch) * DMODEL + d) = s;
}

__global__ __launch_bounds__(DMODEL) void pool_final_kernel(
    const float* __restrict__ part, const int* __restrict__ lens,
    float* __restrict__ out, int out_size)
{
    const int b = blockIdx.x;
    const int d = threadIdx.x;
    float s = 0.0f;
#pragma unroll
    for (int c = 0; c < 8; c++) s += part[(size_t)(b * 8 + c) * DMODEL + d];
    out[b * DMODEL + d] = s / (float)lens[b];
    if (d == 0 && out_size >= BATCH * DMODEL + BATCH)
        out[BATCH * DMODEL + b] = (float)lens[b];
}

// ---------------- launch ------------------------------------------------------
extern "C" void kernel_launch(void* const* d_in, const int* in_sizes, int n_in,
                              void* d_out, int out_size)
{
    (void)in_sizes; (void)n_in;
    const float* x     = (const float*)d_in[0];
    const int*   lens  = (const int*)  d_in[1];
    const float* We    = (const float*)d_in[2];
    const float* be    = (const float*)d_in[3];
    const float* Wqkv  = (const float*)d_in[4];
    const float* bqkv  = (const float*)d_in[5];
    const float* Wo    = (const float*)d_in[6];
    const float* bo    = (const float*)d_in[7];
    const float* ln1g  = (const float*)d_in[8];
    const float* ln1b  = (const float*)d_in[9];
    const float* W1    = (const float*)d_in[10];
    const float* b1    = (const float*)d_in[11];
    const float* W2    = (const float*)d_in[12];
    const float* b2    = (const float*)d_in[13];
    const float* ln2g  = (const float*)d_in[14];
    const float* ln2b  = (const float*)d_in[15];
    float* out = (float*)d_out;

    void *ph, *pht, *pqkv, *pctx, *pff, *ppool;
    void *pwq, *pwo, *pw1, *pw2;
    cudaGetSymbolAddress(&ph,    g_h);
    cudaGetSymbolAddress(&pht,   g_ht);
    cudaGetSymbolAddress(&pqkv,  g_qkv);
    cudaGetSymbolAddress(&pctx,  g_ctx);
    cudaGetSymbolAddress(&pff,   g_ff);
    cudaGetSymbolAddress(&ppool, g_pool);
    cudaGetSymbolAddress(&pwq,   g_wq_r);
    cudaGetSymbolAddress(&pwo,   g_wo_r);
    cudaGetSymbolAddress(&pw1,   g_w1_r);
    cudaGetSymbolAddress(&pw2,   g_w2_r);
    float* h    = (float*)ph;
    float* ht   = (float*)pht;
    float* qkv  = (float*)pqkv;
    float* ctx  = (float*)pctx;
    float* ff   = (float*)pff;
    float* pool = (float*)ppool;
    float* wq_r = (float*)pwq;
    float* wo_r = (float*)pwo;
    float* w1_r = (float*)pw1;
    float* w2_r = (float*)pw2;

    cudaFuncSetAttribute(fattn_kernel,
                         cudaFuncAttributeMaxDynamicSharedMemorySize, ATTN_SMEM);
    cudaFuncSetAttribute(bgemm_kernel<EPI_QKV>,
                         cudaFuncAttributeMaxDynamicSharedMemorySize, GSMEM);
    cudaFuncSetAttribute(bgemm_kernel<EPI_RELU>,
                         cudaFuncAttributeMaxDynamicSharedMemorySize, GSMEM);
    cudaFuncSetAttribute(bgemm_kernel<EPI_RES>,
                         cudaFuncAttributeMaxDynamicSharedMemorySize, GSMEM);

    // ---- round weights to tf32 (once per launch) ----
    round_kernel<<<NLAYERS * 3 * DMODEL * DMODEL / 1024, 256>>>(Wqkv, wq_r);
    round_kernel<<<NLAYERS * DMODEL * DMODEL / 1024, 256>>>(Wo, wo_r);
    round_kernel<<<NLAYERS * DFF * DMODEL / 1024, 256>>>(W1, w1_r);
    round_kernel<<<NLAYERS * DMODEL * DFF / 1024, 256>>>(W2, w2_r);

    // embedding + positional encoding: h (exact) + ht (rounded)
    embed_kernel<<<dim3(DMODEL / 128, NTOK / 128), 256>>>(
        x, We, be, h, ht, NTOK, DMODEL, INSZ);

    for (int l = 0; l < NLAYERS; l++) {
        const float* wq  = wq_r + (size_t)l * 3 * DMODEL * DMODEL;
        const float* bq  = bqkv + (size_t)l * 3 * DMODEL;
        const float* wo  = wo_r + (size_t)l * DMODEL * DMODEL;
        const float* bO  = bo   + (size_t)l * DMODEL;
        const float* w1  = w1_r + (size_t)l * DFF * DMODEL;
        const float* bf1 = b1   + (size_t)l * DFF;
        const float* w2  = w2_r + (size_t)l * DMODEL * DFF;
        const float* bf2 = b2   + (size_t)l * DMODEL;

        // qkv = round(ht @ wq^T + bq)
        bgemm_kernel<EPI_QKV><<<dim3(3 * DMODEL / 128, NTOK / 128), 256, GSMEM>>>(
            ht, wq, bq, nullptr, qkv, NTOK, 3 * DMODEL, DMODEL);

        // attention -> ctx (tf32-rounded)
        fattn_kernel<<<dim3(SMAX / ATQ, NHEAD, BATCH), 256, ATTN_SMEM>>>(qkv, lens, ctx);

        // h = h + ctx @ wo^T + bo
        bgemm_kernel<EPI_RES><<<dim3(DMODEL / 128, NTOK / 128), 256, GSMEM>>>(
            ctx, wo, bO, h, h, NTOK, DMODEL, DMODEL);
        ln_kernel<<<NTOK, 128>>>(h, ln1g + l * DMODEL, ln1b + l * DMODEL, ht);

        // ff = round(relu(ht @ w1^T + b1))
        bgemm_kernel<EPI_RELU><<<dim3(DFF / 128, NTOK / 128), 256, GSMEM>>>(
            ht, w1, bf1, nullptr, ff, NTOK, DFF, DMODEL);
        // h = h + ff @ w2^T + b2
        bgemm_kernel<EPI_RES><<<dim3(DMODEL / 128, NTOK / 128), 256, GSMEM>>>(
            ff, w2, bf2, h, h, NTOK, DMODEL, DFF);
        ln_kernel<<<NTOK, 128>>>(h, ln2g + l * DMODEL, ln2b + l * DMODEL, ht);
    }

    pool_part_kernel<<<dim3(BATCH, 8), 128>>>(h, lens, pool);
    pool_final_kernel<<<BATCH, DMODEL>>>(pool, lens, out, out_size);
}